// round 12
// baseline (speedup 1.0000x reference)
#include <cuda_runtime.h>
#include <math.h>

#define NN 2048
#define AA 100
#define BB 64
#define NTILE 32           // NN / BB (FW band grid)
#define OUT_SUM (NN*AA)
#define OUT_G   (NN*AA+1)
#define ASTR 132
// 65 rows (64 + 1 prefetch-pad) for both panels
#define P3_SMEM ((65*ASTR + 65*128) * (int)sizeof(float))   // 67600 B

// Scratch (static __device__ arrays — no allocation)
__device__ float d_dist[NN*NN];       // 16 MB distance matrix
__device__ int   d_anchors[AA];
__device__ float d_weighted[NN*AA];
__device__ float d_xx[NN];
__device__ float d_rowsum[NN];

__device__ __forceinline__ float finf() { return __int_as_float(0x7f800000); }

// ---------------------------------------------------------------------------
// Build w: adj = motif * nw[i] (row-scaled), w = min(f(adj), f(adj^T)), diag 0
// ---------------------------------------------------------------------------
__global__ void __launch_bounds__(256) k_build_w(const float* __restrict__ m,
                                                 const float* __restrict__ nw) {
    __shared__ float sT[32][33];
    int bi = blockIdx.y, bj = blockIdx.x;
    int tx = threadIdx.x & 31;
    int ty = threadIdx.x >> 5;
    #pragma unroll
    for (int rr = ty; rr < 32; rr += 8)
        sT[rr][tx] = m[(bj*32 + rr)*NN + bi*32 + tx];
    __syncthreads();
    #pragma unroll
    for (int rr = ty; rr < 32; rr += 8) {
        int i = bi*32 + rr;
        int j = bj*32 + tx;
        float a = m[i*NN + j] * nw[i];
        float b = sT[tx][rr] * nw[j];
        float wa = a > 0.f ? a : finf();
        float wb = b > 0.f ? b : finf();
        float w = fminf(wa, wb);
        if (i == j) w = 0.f;
        d_dist[i*NN + j] = w;
    }
}

// ---------------------------------------------------------------------------
// Fused phase1+2 (band k): all 64 blocks redundantly close pivot (k,k) in
// smem, then bid<32 updates row panel (k,o), bid>=32 col panel (o,k).
// (R4-proven version, unchanged.)
// ---------------------------------------------------------------------------
__global__ void __launch_bounds__(256) fw_p12(int k) {
    __shared__ float Ps[BB][BB + 4];
    __shared__ float B1[BB][BB + 4];
    int tid = threadIdx.x;
    const int kB = k * BB;
    const int pbase = kB * NN + kB;

    #pragma unroll
    for (int e = tid; e < BB * BB; e += 256)
        Ps[e >> 6][e & 63] = d_dist[pbase + (e >> 6) * NN + (e & 63)];
    __syncthreads();

    int r  = tid >> 2;
    int c0 = (tid & 3) << 4;
    float cur[16];
    #pragma unroll
    for (int x = 0; x < 16; x++) cur[x] = Ps[r][c0 + x];

    for (int kk = 0; kk < BB; kk++) {
        float a = Ps[r][kk];
        float bv[16];
        #pragma unroll
        for (int q = 0; q < 4; q++) {
            float4 v = *(const float4*)&Ps[kk][c0 + q * 4];
            bv[q*4+0] = v.x; bv[q*4+1] = v.y; bv[q*4+2] = v.z; bv[q*4+3] = v.w;
        }
        #pragma unroll
        for (int x = 0; x < 16; x++)
            cur[x] = fminf(cur[x], a + bv[x]);
        #pragma unroll
        for (int q = 0; q < 4; q++)
            *(float4*)&Ps[r][c0 + q * 4] =
                make_float4(cur[q*4+0], cur[q*4+1], cur[q*4+2], cur[q*4+3]);
        __syncthreads();
    }

    int bid = blockIdx.x;
    int o = bid & 31;
    int tx = tid & 15, ty = tid >> 4;
    int rr0 = ty << 2, cc0 = tx << 2;
    float acc[4][4];
    #pragma unroll
    for (int a = 0; a < 4; a++)
        #pragma unroll
        for (int b = 0; b < 4; b++) acc[a][b] = finf();

    if (bid < 32) {
        #pragma unroll
        for (int x = 0; x < 16; x++) B1[c0 + x][r] = cur[x];   // P*^T
        #pragma unroll
        for (int e = tid; e < BB * BB; e += 256)
            Ps[e >> 6][e & 63] = d_dist[(kB + (e >> 6)) * NN + o * BB + (e & 63)];
        __syncthreads();
        #pragma unroll 4
        for (int p = 0; p < BB; p++) {
            float4 a4 = *(const float4*)&B1[p][rr0];
            float4 b4 = *(const float4*)&Ps[p][cc0];
            float av[4] = {a4.x, a4.y, a4.z, a4.w};
            float bv[4] = {b4.x, b4.y, b4.z, b4.w};
            #pragma unroll
            for (int a = 0; a < 4; a++)
                #pragma unroll
                for (int b = 0; b < 4; b++)
                    acc[a][b] = fminf(acc[a][b], av[a] + bv[b]);
        }
        #pragma unroll
        for (int a = 0; a < 4; a++)
            *(float4*)&d_dist[(kB + rr0 + a) * NN + o * BB + cc0] =
                make_float4(acc[a][0], acc[a][1], acc[a][2], acc[a][3]);
    } else {
        #pragma unroll
        for (int e = tid; e < BB * BB; e += 256) {
            int ii = e >> 6, p = e & 63;
            B1[p][ii] = d_dist[(o * BB + ii) * NN + kB + p];
        }
        __syncthreads();
        #pragma unroll 4
        for (int p = 0; p < BB; p++) {
            float4 a4 = *(const float4*)&B1[p][rr0];
            float4 b4 = *(const float4*)&Ps[p][cc0];
            float av[4] = {a4.x, a4.y, a4.z, a4.w};
            float bv[4] = {b4.x, b4.y, b4.z, b4.w};
            #pragma unroll
            for (int a = 0; a < 4; a++)
                #pragma unroll
                for (int b = 0; b < 4; b++)
                    acc[a][b] = fminf(acc[a][b], av[a] + bv[b]);
        }
        #pragma unroll
        for (int a = 0; a < 4; a++)
            *(float4*)&d_dist[(o * BB + rr0 + a) * NN + kB + cc0] =
                make_float4(acc[a][0], acc[a][1], acc[a][2], acc[a][3]);
    }
}

// ---------------------------------------------------------------------------
// Bulk phase3 (R4 tile shape + software pipelining): 128x128 C tiles,
// K=64 panel, 8x8 microtile, prefetch p+1's smem operands during p's fp ops.
// Panels padded to 65 rows so the p+1 prefetch is always in-bounds.
// ---------------------------------------------------------------------------
__global__ void __launch_bounds__(256, 2) fw_rest(int k) {
    extern __shared__ float sm[];
    float* AsT = sm;                    // [65][ASTR]  AsT[p][i]
    float* Bs  = sm + 65 * ASTR;        // [65][128]   Bs[p][j]
    int tid = threadIdx.x;
    int bx = blockIdx.x, by = blockIdx.y;
    const int kB = k * BB;

    // A: 128 rows x 64 cols, stored transposed
    #pragma unroll
    for (int e = tid; e < 128 * 64; e += 256) {
        int rr = e >> 6, p = e & 63;
        AsT[p * ASTR + rr] = d_dist[(by * 128 + rr) * NN + kB + p];
    }
    // B: 64 rows x 128 cols
    #pragma unroll
    for (int e = tid; e < 64 * 128; e += 256) {
        int p = e >> 7, j = e & 127;
        Bs[p * 128 + j] = d_dist[(kB + p) * NN + bx * 128 + j];
    }
    // pad row 64 (read by the final prefetch; values unused)
    if (tid < 128) {
        AsT[64 * ASTR + tid] = 0.f;
        Bs [64 * 128 + tid] = 0.f;
    }

    int tx = tid & 15, ty = tid >> 4;
    int r0 = ty << 3, c0 = tx << 3;
    const int cbase = (by * 128 + r0) * NN + bx * 128 + c0;
    float acc[8][8];
    #pragma unroll
    for (int a = 0; a < 8; a++) {
        float4 v0 = *(const float4*)&d_dist[cbase + a * NN];
        float4 v1 = *(const float4*)&d_dist[cbase + a * NN + 4];
        acc[a][0] = v0.x; acc[a][1] = v0.y; acc[a][2] = v0.z; acc[a][3] = v0.w;
        acc[a][4] = v1.x; acc[a][5] = v1.y; acc[a][6] = v1.z; acc[a][7] = v1.w;
    }
    __syncthreads();

    const float* aBase = &AsT[r0];
    const float* bBase = &Bs[c0];

    // Software pipeline: prime p=0, then each iteration prefetches p+1
    // before consuming p's operands.
    float4 ca0 = *(const float4*)(aBase);
    float4 ca1 = *(const float4*)(aBase + 4);
    float4 cb0 = *(const float4*)(bBase);
    float4 cb1 = *(const float4*)(bBase + 4);

    #pragma unroll 2
    for (int p = 0; p < BB; p++) {
        const float* aNext = aBase + (p + 1) * ASTR;
        const float* bNext = bBase + (p + 1) * 128;
        float4 na0 = *(const float4*)(aNext);
        float4 na1 = *(const float4*)(aNext + 4);
        float4 nb0 = *(const float4*)(bNext);
        float4 nb1 = *(const float4*)(bNext + 4);

        float av[8] = {ca0.x, ca0.y, ca0.z, ca0.w, ca1.x, ca1.y, ca1.z, ca1.w};
        float bv[8] = {cb0.x, cb0.y, cb0.z, cb0.w, cb1.x, cb1.y, cb1.z, cb1.w};
        #pragma unroll
        for (int a = 0; a < 8; a++)
            #pragma unroll
            for (int b = 0; b < 8; b++)
                acc[a][b] = fminf(acc[a][b], av[a] + bv[b]);

        ca0 = na0; ca1 = na1; cb0 = nb0; cb1 = nb1;
    }

    #pragma unroll
    for (int a = 0; a < 8; a++) {
        *(float4*)&d_dist[cbase + a * NN] =
            make_float4(acc[a][0], acc[a][1], acc[a][2], acc[a][3]);
        *(float4*)&d_dist[cbase + a * NN + 4] =
            make_float4(acc[a][4], acc[a][5], acc[a][6], acc[a][7]);
    }
}

// ---------------------------------------------------------------------------
// Anchors: exact stable argsort(-nw)[:100] via rank counting
// ---------------------------------------------------------------------------
__global__ void k_anchors(const float* __restrict__ nw) {
    __shared__ float s[NN];
    int tid = threadIdx.x;
    for (int e = tid; e < NN; e += 256) s[e] = nw[e];
    __syncthreads();
    int i = blockIdx.x * 256 + tid;
    float v = s[i];
    int rank = 0;
    for (int j = 0; j < NN; j++) {
        float u = s[j];
        rank += (u > v) || (u == v && j < i);
    }
    if (rank < AA) d_anchors[rank] = i;
}

// ---------------------------------------------------------------------------
__global__ void k_gather(const float* __restrict__ wm, float* __restrict__ out) {
    __shared__ int anc[AA];
    __shared__ float r1[128], r2[128];
    int i = blockIdx.x, tid = threadIdx.x;
    if (tid < AA) anc[tid] = d_anchors[tid];
    __syncthreads();
    float cv = 0.f, wsq = 0.f;
    if (tid < AA) {
        float v = d_dist[i * NN + anc[tid]];
        if (v > 3.0e38f) v = 100.f;
        out[i * AA + tid] = v;
        float w = wm[i * AA + tid] * v;
        d_weighted[i * AA + tid] = w;
        cv = v; wsq = w * w;
    }
    r1[tid] = cv; r2[tid] = wsq;
    __syncthreads();
    for (int st = 64; st > 0; st >>= 1) {
        if (tid < st) { r1[tid] += r1[tid + st]; r2[tid] += r2[tid + st]; }
        __syncthreads();
    }
    if (tid == 0) { d_rowsum[i] = r1[0]; d_xx[i] = r2[0]; }
}

__global__ void k_finalize(float* __restrict__ out) {
    __shared__ float red[256];
    int tid = threadIdx.x;
    float s = 0.f;
    for (int e = tid; e < NN; e += 256) s += d_rowsum[e];
    red[tid] = s;
    __syncthreads();
    for (int st = 128; st > 0; st >>= 1) {
        if (tid < st) red[tid] += red[tid + st];
        __syncthreads();
    }
    if (tid == 0) out[OUT_SUM] = (red[0] - 100.f * NN) / ((float)NN * AA);
}

// ---------------------------------------------------------------------------
__global__ void __launch_bounds__(256) k_graph(const float* __restrict__ sigma_p,
                                               float* __restrict__ out) {
    __shared__ float WiT[32][BB + 4];
    __shared__ float WjT[32][BB + 4];
    int bx = blockIdx.x, by = blockIdx.y;
    int tid = threadIdx.x, tx = tid & 15, ty = tid >> 4;
    int r0 = ty << 2, c0 = tx << 2;
    float acc[4][4] = {};
    for (int k0 = 0; k0 < 128; k0 += 32) {
        for (int e = tid; e < BB * 32; e += 256) {
            int rr = e >> 5, kc = e & 31;
            int kg = k0 + kc;
            float wi = 0.f, wj = 0.f;
            if (kg < AA) {
                wi = d_weighted[(by * BB + rr) * AA + kg];
                wj = d_weighted[(bx * BB + rr) * AA + kg];
            }
            WiT[kc][rr] = wi; WjT[kc][rr] = wj;
        }
        __syncthreads();
        #pragma unroll
        for (int kc = 0; kc < 32; kc++) {
            float4 a4 = *(const float4*)&WiT[kc][r0];
            float4 b4 = *(const float4*)&WjT[kc][c0];
            float av[4] = {a4.x, a4.y, a4.z, a4.w};
            float bv[4] = {b4.x, b4.y, b4.z, b4.w};
            #pragma unroll
            for (int a = 0; a < 4; a++)
                #pragma unroll
                for (int b = 0; b < 4; b++)
                    acc[a][b] += av[a] * bv[b];
        }
        __syncthreads();
    }
    float sg = *sigma_p;
    float inv2 = 0.5f / (sg * sg);
    float xi[4], xj[4];
    #pragma unroll
    for (int a = 0; a < 4; a++) xi[a] = d_xx[by * BB + r0 + a];
    #pragma unroll
    for (int b = 0; b < 4; b++) xj[b] = d_xx[bx * BB + c0 + b];
    #pragma unroll
    for (int a = 0; a < 4; a++) {
        int i = by * BB + r0 + a;
        #pragma unroll
        for (int b = 0; b < 4; b++) {
            int j = bx * BB + c0 + b;
            float sq = xi[a] + xj[b] - 2.f * acc[a][b];
            sq = fmaxf(sq, 0.f);
            out[OUT_G + i * NN + j] = expf(-(sq * sq) * inv2);
        }
    }
}

// ---------------------------------------------------------------------------
extern "C" void kernel_launch(void* const* d_in, const int* in_sizes, int n_in,
                              void* d_out, int out_size) {
    const float* m  = (const float*)d_in[0];
    const float* nw = (const float*)d_in[1];
    const float* wm = (const float*)d_in[2];
    const float* sg = (const float*)d_in[3];
    float* out = (float*)d_out;

    static int inited = 0;
    if (!inited) {
        cudaFuncSetAttribute(fw_rest,
                             cudaFuncAttributeMaxDynamicSharedMemorySize, P3_SMEM);
        inited = 1;
    }

    k_build_w<<<dim3(NN/32, NN/32), 256>>>(m, nw);
    k_anchors<<<NN / 256, 256>>>(nw);

    for (int k = 0; k < NTILE; k++) {
        fw_p12<<<64, 256>>>(k);
        fw_rest<<<dim3(16, 16), 256, P3_SMEM>>>(k);
    }

    k_gather<<<NN, 128>>>(wm, out);
    k_finalize<<<1, 256>>>(out);
    k_graph<<<dim3(NTILE, NTILE), 256>>>(sg, out);
}

// round 13
// speedup vs baseline: 1.0320x; 1.0320x over previous
#include <cuda_runtime.h>
#include <math.h>

#define NN 2048
#define AA 100
#define BB 64
#define NTILE 32           // NN / BB (FW band grid)
#define OUT_SUM (NN*AA)
#define OUT_G   (NN*AA+1)
#define ASTR 132
#define P3_SMEM ((BB*ASTR + BB*128) * (int)sizeof(float))   // 66560 B

// Scratch (static __device__ arrays — no allocation)
__device__ float d_dist[NN*NN];       // 16 MB distance matrix
__device__ int   d_anchors[AA];
__device__ float d_weighted[NN*AA];
__device__ float d_xx[NN];
__device__ float d_rowsum[NN];

__device__ __forceinline__ float finf() { return __int_as_float(0x7f800000); }

// Runtime-opaque 1.0f (k >= 0 always, but the compiler can't prove it),
// so __fmaf_rn(a, one, b) stays an FFMA (fma pipe) instead of being
// strength-reduced to FADD (which the scheduler parks on the alu pipe,
// fighting FMNMX for the same 0.5/cyc/SMSP slot).
__device__ __forceinline__ float opaque_one(int k) {
    return __int_as_float(0x3f800000 + (k >> 31));
}

// ---------------------------------------------------------------------------
// Build w: adj = motif * nw[i] (row-scaled), w = min(f(adj), f(adj^T)), diag 0
// ---------------------------------------------------------------------------
__global__ void __launch_bounds__(256) k_build_w(const float* __restrict__ m,
                                                 const float* __restrict__ nw) {
    __shared__ float sT[32][33];
    int bi = blockIdx.y, bj = blockIdx.x;
    int tx = threadIdx.x & 31;
    int ty = threadIdx.x >> 5;
    #pragma unroll
    for (int rr = ty; rr < 32; rr += 8)
        sT[rr][tx] = m[(bj*32 + rr)*NN + bi*32 + tx];
    __syncthreads();
    #pragma unroll
    for (int rr = ty; rr < 32; rr += 8) {
        int i = bi*32 + rr;
        int j = bj*32 + tx;
        float a = m[i*NN + j] * nw[i];
        float b = sT[tx][rr] * nw[j];
        float wa = a > 0.f ? a : finf();
        float wb = b > 0.f ? b : finf();
        float w = fminf(wa, wb);
        if (i == j) w = 0.f;
        d_dist[i*NN + j] = w;
    }
}

// ---------------------------------------------------------------------------
// Fused phase1+2 (band k): all 64 blocks redundantly close pivot (k,k) in
// smem, then bid<32 updates row panel (k,o), bid>=32 col panel (o,k).
// GEMM loops use the FFMA-add trick; closure stays scalar (latency-bound).
// ---------------------------------------------------------------------------
__global__ void __launch_bounds__(256) fw_p12(int k) {
    __shared__ float Ps[BB][BB + 4];
    __shared__ float B1[BB][BB + 4];
    int tid = threadIdx.x;
    const int kB = k * BB;
    const int pbase = kB * NN + kB;
    const float one = opaque_one(k);

    #pragma unroll
    for (int e = tid; e < BB * BB; e += 256)
        Ps[e >> 6][e & 63] = d_dist[pbase + (e >> 6) * NN + (e & 63)];
    __syncthreads();

    int r  = tid >> 2;
    int c0 = (tid & 3) << 4;
    float cur[16];
    #pragma unroll
    for (int x = 0; x < 16; x++) cur[x] = Ps[r][c0 + x];

    for (int kk = 0; kk < BB; kk++) {
        float a = Ps[r][kk];
        float bv[16];
        #pragma unroll
        for (int q = 0; q < 4; q++) {
            float4 v = *(const float4*)&Ps[kk][c0 + q * 4];
            bv[q*4+0] = v.x; bv[q*4+1] = v.y; bv[q*4+2] = v.z; bv[q*4+3] = v.w;
        }
        #pragma unroll
        for (int x = 0; x < 16; x++)
            cur[x] = fminf(cur[x], a + bv[x]);
        #pragma unroll
        for (int q = 0; q < 4; q++)
            *(float4*)&Ps[r][c0 + q * 4] =
                make_float4(cur[q*4+0], cur[q*4+1], cur[q*4+2], cur[q*4+3]);
        __syncthreads();
    }

    int bid = blockIdx.x;
    int o = bid & 31;
    int tx = tid & 15, ty = tid >> 4;
    int rr0 = ty << 2, cc0 = tx << 2;
    float acc[4][4];
    #pragma unroll
    for (int a = 0; a < 4; a++)
        #pragma unroll
        for (int b = 0; b < 4; b++) acc[a][b] = finf();

    if (bid < 32) {
        #pragma unroll
        for (int x = 0; x < 16; x++) B1[c0 + x][r] = cur[x];   // P*^T
        #pragma unroll
        for (int e = tid; e < BB * BB; e += 256)
            Ps[e >> 6][e & 63] = d_dist[(kB + (e >> 6)) * NN + o * BB + (e & 63)];
        __syncthreads();
        #pragma unroll 4
        for (int p = 0; p < BB; p++) {
            float4 a4 = *(const float4*)&B1[p][rr0];
            float4 b4 = *(const float4*)&Ps[p][cc0];
            float av[4] = {a4.x, a4.y, a4.z, a4.w};
            float bv[4] = {b4.x, b4.y, b4.z, b4.w};
            #pragma unroll
            for (int a = 0; a < 4; a++)
                #pragma unroll
                for (int b = 0; b < 4; b++)
                    acc[a][b] = fminf(acc[a][b], __fmaf_rn(av[a], one, bv[b]));
        }
        #pragma unroll
        for (int a = 0; a < 4; a++)
            *(float4*)&d_dist[(kB + rr0 + a) * NN + o * BB + cc0] =
                make_float4(acc[a][0], acc[a][1], acc[a][2], acc[a][3]);
    } else {
        #pragma unroll
        for (int e = tid; e < BB * BB; e += 256) {
            int ii = e >> 6, p = e & 63;
            B1[p][ii] = d_dist[(o * BB + ii) * NN + kB + p];
        }
        __syncthreads();
        #pragma unroll 4
        for (int p = 0; p < BB; p++) {
            float4 a4 = *(const float4*)&B1[p][rr0];
            float4 b4 = *(const float4*)&Ps[p][cc0];
            float av[4] = {a4.x, a4.y, a4.z, a4.w};
            float bv[4] = {b4.x, b4.y, b4.z, b4.w};
            #pragma unroll
            for (int a = 0; a < 4; a++)
                #pragma unroll
                for (int b = 0; b < 4; b++)
                    acc[a][b] = fminf(acc[a][b], __fmaf_rn(av[a], one, bv[b]));
        }
        #pragma unroll
        for (int a = 0; a < 4; a++)
            *(float4*)&d_dist[(o * BB + rr0 + a) * NN + kB + cc0] =
                make_float4(acc[a][0], acc[a][1], acc[a][2], acc[a][3]);
    }
}

// ---------------------------------------------------------------------------
// Bulk phase3 (exact R4 shape): 128x128 C tiles, K=64 panel, 8x8 microtile.
// adds forced onto the fma pipe via FFMA(av, one, bv); mins on alu pipe.
// ---------------------------------------------------------------------------
__global__ void __launch_bounds__(256, 2) fw_rest(int k) {
    extern __shared__ float sm[];
    float* AsT = sm;                    // [64][ASTR]  AsT[p][i]
    float* Bs  = sm + BB * ASTR;        // [64][128]   Bs[p][j]
    int tid = threadIdx.x;
    int bx = blockIdx.x, by = blockIdx.y;
    const int kB = k * BB;
    const float one = opaque_one(k);

    #pragma unroll
    for (int e = tid; e < 128 * 64; e += 256) {
        int rr = e >> 6, p = e & 63;
        AsT[p * ASTR + rr] = d_dist[(by * 128 + rr) * NN + kB + p];
    }
    #pragma unroll
    for (int e = tid; e < 64 * 128; e += 256) {
        int p = e >> 7, j = e & 127;
        Bs[p * 128 + j] = d_dist[(kB + p) * NN + bx * 128 + j];
    }

    int tx = tid & 15, ty = tid >> 4;
    int r0 = ty << 3, c0 = tx << 3;
    const int cbase = (by * 128 + r0) * NN + bx * 128 + c0;
    float acc[8][8];
    #pragma unroll
    for (int a = 0; a < 8; a++) {
        float4 v0 = *(const float4*)&d_dist[cbase + a * NN];
        float4 v1 = *(const float4*)&d_dist[cbase + a * NN + 4];
        acc[a][0] = v0.x; acc[a][1] = v0.y; acc[a][2] = v0.z; acc[a][3] = v0.w;
        acc[a][4] = v1.x; acc[a][5] = v1.y; acc[a][6] = v1.z; acc[a][7] = v1.w;
    }
    __syncthreads();

    #pragma unroll 4
    for (int p = 0; p < BB; p++) {
        float4 a0 = *(const float4*)&AsT[p * ASTR + r0];
        float4 a1 = *(const float4*)&AsT[p * ASTR + r0 + 4];
        float4 b0 = *(const float4*)&Bs[p * 128 + c0];
        float4 b1 = *(const float4*)&Bs[p * 128 + c0 + 4];
        float av[8] = {a0.x, a0.y, a0.z, a0.w, a1.x, a1.y, a1.z, a1.w};
        float bv[8] = {b0.x, b0.y, b0.z, b0.w, b1.x, b1.y, b1.z, b1.w};
        #pragma unroll
        for (int a = 0; a < 8; a++)
            #pragma unroll
            for (int b = 0; b < 8; b++)
                acc[a][b] = fminf(acc[a][b], __fmaf_rn(av[a], one, bv[b]));
    }

    #pragma unroll
    for (int a = 0; a < 8; a++) {
        *(float4*)&d_dist[cbase + a * NN] =
            make_float4(acc[a][0], acc[a][1], acc[a][2], acc[a][3]);
        *(float4*)&d_dist[cbase + a * NN + 4] =
            make_float4(acc[a][4], acc[a][5], acc[a][6], acc[a][7]);
    }
}

// ---------------------------------------------------------------------------
// Anchors: exact stable argsort(-nw)[:100] via rank counting
// ---------------------------------------------------------------------------
__global__ void k_anchors(const float* __restrict__ nw) {
    __shared__ float s[NN];
    int tid = threadIdx.x;
    for (int e = tid; e < NN; e += 256) s[e] = nw[e];
    __syncthreads();
    int i = blockIdx.x * 256 + tid;
    float v = s[i];
    int rank = 0;
    for (int j = 0; j < NN; j++) {
        float u = s[j];
        rank += (u > v) || (u == v && j < i);
    }
    if (rank < AA) d_anchors[rank] = i;
}

// ---------------------------------------------------------------------------
__global__ void k_gather(const float* __restrict__ wm, float* __restrict__ out) {
    __shared__ int anc[AA];
    __shared__ float r1[128], r2[128];
    int i = blockIdx.x, tid = threadIdx.x;
    if (tid < AA) anc[tid] = d_anchors[tid];
    __syncthreads();
    float cv = 0.f, wsq = 0.f;
    if (tid < AA) {
        float v = d_dist[i * NN + anc[tid]];
        if (v > 3.0e38f) v = 100.f;
        out[i * AA + tid] = v;
        float w = wm[i * AA + tid] * v;
        d_weighted[i * AA + tid] = w;
        cv = v; wsq = w * w;
    }
    r1[tid] = cv; r2[tid] = wsq;
    __syncthreads();
    for (int st = 64; st > 0; st >>= 1) {
        if (tid < st) { r1[tid] += r1[tid + st]; r2[tid] += r2[tid + st]; }
        __syncthreads();
    }
    if (tid == 0) { d_rowsum[i] = r1[0]; d_xx[i] = r2[0]; }
}

__global__ void k_finalize(float* __restrict__ out) {
    __shared__ float red[256];
    int tid = threadIdx.x;
    float s = 0.f;
    for (int e = tid; e < NN; e += 256) s += d_rowsum[e];
    red[tid] = s;
    __syncthreads();
    for (int st = 128; st > 0; st >>= 1) {
        if (tid < st) red[tid] += red[tid + st];
        __syncthreads();
    }
    if (tid == 0) out[OUT_SUM] = (red[0] - 100.f * NN) / ((float)NN * AA);
}

// ---------------------------------------------------------------------------
__global__ void __launch_bounds__(256) k_graph(const float* __restrict__ sigma_p,
                                               float* __restrict__ out) {
    __shared__ float WiT[32][BB + 4];
    __shared__ float WjT[32][BB + 4];
    int bx = blockIdx.x, by = blockIdx.y;
    int tid = threadIdx.x, tx = tid & 15, ty = tid >> 4;
    int r0 = ty << 2, c0 = tx << 2;
    float acc[4][4] = {};
    for (int k0 = 0; k0 < 128; k0 += 32) {
        for (int e = tid; e < BB * 32; e += 256) {
            int rr = e >> 5, kc = e & 31;
            int kg = k0 + kc;
            float wi = 0.f, wj = 0.f;
            if (kg < AA) {
                wi = d_weighted[(by * BB + rr) * AA + kg];
                wj = d_weighted[(bx * BB + rr) * AA + kg];
            }
            WiT[kc][rr] = wi; WjT[kc][rr] = wj;
        }
        __syncthreads();
        #pragma unroll
        for (int kc = 0; kc < 32; kc++) {
            float4 a4 = *(const float4*)&WiT[kc][r0];
            float4 b4 = *(const float4*)&WjT[kc][c0];
            float av[4] = {a4.x, a4.y, a4.z, a4.w};
            float bv[4] = {b4.x, b4.y, b4.z, b4.w};
            #pragma unroll
            for (int a = 0; a < 4; a++)
                #pragma unroll
                for (int b = 0; b < 4; b++)
                    acc[a][b] += av[a] * bv[b];
        }
        __syncthreads();
    }
    float sg = *sigma_p;
    float inv2 = 0.5f / (sg * sg);
    float xi[4], xj[4];
    #pragma unroll
    for (int a = 0; a < 4; a++) xi[a] = d_xx[by * BB + r0 + a];
    #pragma unroll
    for (int b = 0; b < 4; b++) xj[b] = d_xx[bx * BB + c0 + b];
    #pragma unroll
    for (int a = 0; a < 4; a++) {
        int i = by * BB + r0 + a;
        #pragma unroll
        for (int b = 0; b < 4; b++) {
            int j = bx * BB + c0 + b;
            float sq = xi[a] + xj[b] - 2.f * acc[a][b];
            sq = fmaxf(sq, 0.f);
            out[OUT_G + i * NN + j] = expf(-(sq * sq) * inv2);
        }
    }
}

// ---------------------------------------------------------------------------
extern "C" void kernel_launch(void* const* d_in, const int* in_sizes, int n_in,
                              void* d_out, int out_size) {
    const float* m  = (const float*)d_in[0];
    const float* nw = (const float*)d_in[1];
    const float* wm = (const float*)d_in[2];
    const float* sg = (const float*)d_in[3];
    float* out = (float*)d_out;

    static int inited = 0;
    if (!inited) {
        cudaFuncSetAttribute(fw_rest,
                             cudaFuncAttributeMaxDynamicSharedMemorySize, P3_SMEM);
        inited = 1;
    }

    k_build_w<<<dim3(NN/32, NN/32), 256>>>(m, nw);
    k_anchors<<<NN / 256, 256>>>(nw);

    for (int k = 0; k < NTILE; k++) {
        fw_p12<<<64, 256>>>(k);
        fw_rest<<<dim3(16, 16), 256, P3_SMEM>>>(k);
    }

    k_gather<<<NN, 128>>>(wm, out);
    k_finalize<<<1, 256>>>(out);
    k_graph<<<dim3(NTILE, NTILE), 256>>>(sg, out);
}